// round 8
// baseline (speedup 1.0000x reference)
#include <cuda_runtime.h>
#include <cuda_bf16.h>
#include <cstdint>

typedef __nv_bfloat16 bf16;

#define Bz   32
#define Sz   128
#define Tz   127
#define Vz   32000
#define Ez   512
#define Gz   1024
#define HIz  512
#define G4z  4096
#define MR   4064   /* Tz*Bz */

// ------------------------- static device scratch -------------------------
__device__ bf16  g_Wout_hi[(size_t)Vz*Gz];
__device__ bf16  g_Wout_lo[(size_t)Vz*Gz];
__device__ bf16  g_Wih_hi[(size_t)G4z*Ez];
__device__ bf16  g_Wih_lo[(size_t)G4z*Ez];
__device__ bf16  g_Whh_hi[(size_t)G4z*Gz];
__device__ bf16  g_Whh_lo[(size_t)G4z*Gz];
__device__ bf16  g_H_hi[(size_t)(Tz+1)*Bz*Gz];  // block s = h after step s (block 0 = h0)
__device__ bf16  g_H_lo[(size_t)(Tz+1)*Bz*Gz];
__device__ bf16  g_X_hi[(size_t)MR*Ez];
__device__ bf16  g_X_lo[(size_t)MR*Ez];
__device__ float g_Xg[(size_t)MR*G4z];
__device__ float g_c[Bz*Gz];
__device__ float g_Q[Bz*HIz];
__device__ float g_Kb[Bz*16*HIz];
__device__ float g_Vb[Bz*16*HIz];
__device__ float g_ctx[Bz*HIz];
__device__ float g_att[Bz*HIz];
__device__ float g_ff[Bz*3*HIz];
__device__ float g_ie[Bz*Ez];
__device__ float g_g0[Bz*G4z];
__device__ float g_bsum[G4z];

// ------------------------------ helpers ----------------------------------
__device__ __forceinline__ float sigf(float x){ return 1.0f/(1.0f+expf(-x)); }

__device__ __forceinline__ void ldsmx4(uint32_t* r, const bf16* p){
    uint32_t a = (uint32_t)__cvta_generic_to_shared(p);
    asm volatile("ldmatrix.sync.aligned.m8n8.x4.shared.b16 {%0,%1,%2,%3},[%4];\n"
                 : "=r"(r[0]),"=r"(r[1]),"=r"(r[2]),"=r"(r[3]) : "r"(a));
}
__device__ __forceinline__ void mma16816(float* d, const uint32_t* a, const uint32_t* b){
    asm volatile("mma.sync.aligned.m16n8k16.row.col.f32.bf16.bf16.f32 "
                 "{%0,%1,%2,%3},{%4,%5,%6,%7},{%8,%9},{%0,%1,%2,%3};\n"
                 : "+f"(d[0]),"+f"(d[1]),"+f"(d[2]),"+f"(d[3])
                 : "r"(a[0]),"r"(a[1]),"r"(a[2]),"r"(a[3]),
                   "r"(b[0]),"r"(b[1]));
}

// --------------------------- prep kernels --------------------------------
__global__ void k_split(const float* __restrict__ src, bf16* __restrict__ hi,
                        bf16* __restrict__ lo, int n){
    int i = blockIdx.x*blockDim.x + threadIdx.x;
    if (i < n){
        float x = src[i];
        bf16 h = __float2bfloat16(x);
        hi[i] = h;
        lo[i] = __float2bfloat16(x - __bfloat162float(h));
    }
}

__global__ void k_bsum(const float* __restrict__ a, const float* __restrict__ b){
    int i = blockIdx.x*blockDim.x + threadIdx.x;
    if (i < G4z) g_bsum[i] = a[i] + b[i];
}

__global__ void k_xgather(const float* __restrict__ emb, const int* __restrict__ sent){
    int i = blockIdx.x*blockDim.x + threadIdx.x;
    if (i < MR*Ez){
        int r = i >> 9, col = i & 511;      // Ez = 512
        int t = r >> 5, b = r & 31;
        int idx = sent[b*Sz + t];           // x uses target_sent[:, :-1]
        float v = emb[(size_t)idx*Ez + col];
        bf16 h = __float2bfloat16(v);
        g_X_hi[i] = h;
        g_X_lo[i] = __float2bfloat16(v - __bfloat162float(h));
    }
}

__global__ void k_ff(const float* __restrict__ ent, const float* __restrict__ img){
    int i = blockIdx.x*blockDim.x + threadIdx.x;
    if (i < Bz*HIz){
        int b = i >> 9, j = i & 511;
        float* row = g_ff + (size_t)b*3*HIz;
        row[j]          = ent[i];
        row[HIz + j]    = g_att[i];
        row[2*HIz + j]  = img[i];
    }
}

// ------------------- generic small fp32 GEMM (warp/output) ---------------
// out[m*N+n] = act( sum_k A[m,k]*W[n,k] + bias[n] )
__global__ void k_small(const float* __restrict__ A, const float* __restrict__ W,
                        const float* __restrict__ bias, float* __restrict__ out,
                        int M, int N, int K, int act){
    int gw = (blockIdx.x*blockDim.x + threadIdx.x) >> 5;
    int lane = threadIdx.x & 31;
    if (gw >= M*N) return;
    int m = gw / N, n = gw % N;
    const float* a = A + (size_t)m*K;
    const float* w = W + (size_t)n*K;
    float s = 0.f;
    for (int k = lane; k < K; k += 32) s += a[k]*w[k];
#pragma unroll
    for (int o = 16; o; o >>= 1) s += __shfl_down_sync(0xffffffffu, s, o);
    if (lane == 0){
        s += bias ? bias[n] : 0.f;
        if (act == 1) s = tanhf(s);
        out[(size_t)m*N + n] = s;
    }
}

// ------------------------------ attention --------------------------------
__global__ void k_attn(const int* __restrict__ nnum){
    int bh = blockIdx.x;
    int b = bh >> 3, h = bh & 7;
    int d = threadIdx.x;                    // 64 threads
    __shared__ float red[64];
    __shared__ float sc[16];
    float q = g_Q[b*HIz + h*64 + d];
    for (int n = 0; n < 16; n++){
        red[d] = q * g_Kb[(size_t)(b*16+n)*HIz + h*64 + d];
        __syncthreads();
        for (int o = 32; o; o >>= 1){
            if (d < o) red[d] += red[d+o];
            __syncthreads();
        }
        if (d == 0) sc[n] = red[0]*0.125f;   // 1/sqrt(64)
        __syncthreads();
    }
    int num = nnum[b];
    float a[16], mx = -1e30f;
#pragma unroll
    for (int n = 0; n < 16; n++){
        a[n] = (n >= num) ? -1e9f : sc[n];
        mx = fmaxf(mx, a[n]);
    }
    float ssum = 0.f;
#pragma unroll
    for (int n = 0; n < 16; n++){ a[n] = expf(a[n]-mx); ssum += a[n]; }
    float inv = 1.f/ssum;
    float ctx = 0.f;
#pragma unroll
    for (int n = 0; n < 16; n++)
        ctx += a[n] * g_Vb[(size_t)(b*16+n)*HIz + h*64 + d];
    g_ctx[b*HIz + h*64 + d] = ctx*inv;
}

// --------------------------- first LSTM step -----------------------------
__global__ void k_step0(){
    int i = blockIdx.x*blockDim.x + threadIdx.x;
    if (i < Bz*Gz){
        int b = i >> 10, j = i & 1023;
        const float* g0 = g_g0 + (size_t)b*G4z;
        float gi = g0[j], gf = g0[j+Gz], gg = g0[j+2*Gz], go = g0[j+3*Gz];
        (void)gf; // c_prev = 0
        float c = sigf(gi)*tanhf(gg);
        float h = sigf(go)*tanhf(c);
        g_c[i] = c;
        bf16 hh = __float2bfloat16(h);
        g_H_hi[i] = hh;
        g_H_lo[i] = __float2bfloat16(h - __bfloat162float(hh));
    }
}

// ----------------- fused recurrence step (MMA + LSTM cell) ---------------
// 64 blocks x 128 threads. Block nb owns gate cols {nb*16..+15} in all 4
// quadrants (warp q = quadrant q). Computes h_prev @ W_hh^T for its 64 gate
// rows, adds precomputed Xg, applies cell update, writes h (bf16 hi/lo).
#define SLD 72
__global__ void __launch_bounds__(128, 1) k_step(int s){
    __shared__ bf16 sA[2][32*SLD];
    __shared__ bf16 sB[2][64*SLD];
    __shared__ float sG[4][32][16];
    const int tid = threadIdx.x, warp = tid >> 5, lane = tid & 31;
    const int nb = blockIdx.x;
    const bf16* hHi = g_H_hi + (size_t)s*Bz*Gz;
    const bf16* hLo = g_H_lo + (size_t)s*Bz*Gz;
    bf16* oHi = g_H_hi + (size_t)(s+1)*Bz*Gz;
    bf16* oLo = g_H_lo + (size_t)(s+1)*Bz*Gz;
    const float* Xg = g_Xg + (size_t)s*Bz*G4z;

    float acc[2][2][4];
#pragma unroll
    for (int a=0;a<2;a++)
#pragma unroll
    for (int b=0;b<2;b++)
#pragma unroll
    for (int c=0;c<4;c++) acc[a][b][c]=0.f;

    for (int kk = 0; kk < Gz; kk += 64){
#pragma unroll
        for (int i = 0; i < 2; i++){        // A: 32x64 -> 256 uint4 per matrix
            int u = tid + i*128;
            int r = u >> 3, c = (u & 7)*8;
            *(uint4*)&sA[0][r*SLD+c] = *(const uint4*)(hHi + (size_t)r*Gz + kk + c);
            *(uint4*)&sA[1][r*SLD+c] = *(const uint4*)(hLo + (size_t)r*Gz + kk + c);
        }
#pragma unroll
        for (int i = 0; i < 4; i++){        // B: 64x64 -> 512 uint4 per matrix
            int u = tid + i*128;
            int r = u >> 3, c = (u & 7)*8;
            int g = (r >> 4)*Gz + nb*16 + (r & 15);
            *(uint4*)&sB[0][r*SLD+c] = *(const uint4*)(g_Whh_hi + (size_t)g*Gz + kk + c);
            *(uint4*)&sB[1][r*SLD+c] = *(const uint4*)(g_Whh_lo + (size_t)g*Gz + kk + c);
        }
        __syncthreads();
#pragma unroll
        for (int ks = 0; ks < 64; ks += 16){
            uint32_t ah[2][4], al[2][4], bh[4], bl[4];
#pragma unroll
            for (int mi = 0; mi < 2; mi++){
                int row = mi*16 + (lane & 15);
                int kc  = ks + (lane >> 4)*8;
                ldsmx4(ah[mi], &sA[0][row*SLD + kc]);
                ldsmx4(al[mi], &sA[1][row*SLD + kc]);
            }
            {
                int j = lane >> 3;
                int row = warp*16 + ((j >> 1)*8) + (lane & 7);
                int kc  = ks + (j & 1)*8;
                ldsmx4(bh, &sB[0][row*SLD + kc]);
                ldsmx4(bl, &sB[1][row*SLD + kc]);
            }
#pragma unroll
            for (int mi = 0; mi < 2; mi++)
#pragma unroll
                for (int nj = 0; nj < 2; nj++){
                    mma16816(acc[mi][nj], ah[mi], &bh[nj*2]);
                    mma16816(acc[mi][nj], ah[mi], &bl[nj*2]);
                    mma16816(acc[mi][nj], al[mi], &bh[nj*2]);
                }
        }
        __syncthreads();
    }
    // scatter accumulators: warp q holds quadrant q values for (b, jl)
#pragma unroll
    for (int mi = 0; mi < 2; mi++)
#pragma unroll
    for (int nj = 0; nj < 2; nj++)
#pragma unroll
    for (int h = 0; h < 2; h++){
        int b  = mi*16 + (lane >> 2) + h*8;
        int jl = nj*8 + (lane & 3)*2;
        sG[warp][b][jl]   = acc[mi][nj][h*2];
        sG[warp][b][jl+1] = acc[mi][nj][h*2+1];
    }
    __syncthreads();
    // LSTM cell update for 32x16 elements
    for (int e = tid; e < 512; e += 128){
        int b = e >> 4, jl = e & 15;
        int col = nb*16 + jl;
        const float* xg = Xg + (size_t)b*G4z;
        float gi = sG[0][b][jl] + xg[col];
        float gf = sG[1][b][jl] + xg[col +   Gz];
        float gg = sG[2][b][jl] + xg[col + 2*Gz];
        float go = sG[3][b][jl] + xg[col + 3*Gz];
        float c = sigf(gf)*g_c[b*Gz+col] + sigf(gi)*tanhf(gg);
        float h = sigf(go)*tanhf(c);
        g_c[b*Gz+col] = c;
        bf16 hh = __float2bfloat16(h);
        oHi[b*Gz+col] = hh;
        oLo[b*Gz+col] = __float2bfloat16(h - __bfloat162float(hh));
    }
}

// ------------- big split-bf16 GEMM:  D = A(hi+lo) * B(hi+lo)^T ------------
// 128x128 block tile, BK=32, 8 warps (2x4), warp tile 64x32, 3 MMA terms.
// mode 0: out[m*N+n] = D + bias[n]
// mode 1: logits remap  out[(b*127+t)*N + n],  m = t*32 + b
#define LDT 40
__global__ void __launch_bounds__(256, 1) k_gemm3(
    const bf16* __restrict__ Ahi, const bf16* __restrict__ Alo,
    const bf16* __restrict__ Bhi, const bf16* __restrict__ Blo,
    const float* __restrict__ bias, float* __restrict__ out,
    int M, int N, int K, int mode)
{
    __shared__ bf16 sA[2][128*LDT];
    __shared__ bf16 sB[2][128*LDT];
    const int tid = threadIdx.x, warp = tid >> 5, lane = tid & 31;
    const int m0 = blockIdx.x*128, n0 = blockIdx.y*128;
    const int wm = (warp >> 2)*64, wn = (warp & 3)*32;

    float acc[4][4][4];
#pragma unroll
    for (int a=0;a<4;a++)
#pragma unroll
    for (int b=0;b<4;b++)
#pragma unroll
    for (int c=0;c<4;c++) acc[a][b][c]=0.f;

    for (int kk = 0; kk < K; kk += 32){
#pragma unroll
        for (int i = 0; i < 2; i++){
            int u = tid + i*256;            // 0..511
            int r = u >> 2, c = (u & 3)*8;
            int gr = m0 + r;
            uint4 vh = make_uint4(0,0,0,0), vl = make_uint4(0,0,0,0);
            if (gr < M){
                vh = *(const uint4*)(Ahi + (size_t)gr*K + kk + c);
                vl = *(const uint4*)(Alo + (size_t)gr*K + kk + c);
            }
            *(uint4*)&sA[0][r*LDT+c] = vh;
            *(uint4*)&sA[1][r*LDT+c] = vl;
            int gn = n0 + r;                // N is multiple of 128 in both uses
            *(uint4*)&sB[0][r*LDT+c] = *(const uint4*)(Bhi + (size_t)gn*K + kk + c);
            *(uint4*)&sB[1][r*LDT+c] = *(const uint4*)(Blo + (size_t)gn*K + kk + c);
        }
        __syncthreads();
#pragma unroll
        for (int ks = 0; ks < 32; ks += 16){
            uint32_t ah[4][4], al[4][4], bh[2][4], bl[2][4];
#pragma unroll
            for (int mi = 0; mi < 4; mi++){
                int row = wm + mi*16 + (lane & 15);
                int kc  = ks + (lane >> 4)*8;
                ldsmx4(ah[mi], &sA[0][row*LDT + kc]);
                ldsmx4(al[mi], &sA[1][row*LDT + kc]);
            }
#pragma unroll
            for (int ni = 0; ni < 2; ni++){
                int j = lane >> 3;
                int row = wn + ni*16 + ((j >> 1)*8) + (lane & 7);
                int kc  = ks + (j & 1)*8;
                ldsmx4(bh[ni], &sB[0][row*LDT + kc]);
                ldsmx4(bl[ni], &sB[1][row*LDT + kc]);
            }
#pragma unroll
            for (int mi = 0; mi < 4; mi++)
#pragma unroll
                for (int nj = 0; nj < 4; nj++){
                    const uint32_t* fh = &bh[nj >> 1][(nj & 1)*2];
                    const uint32_t* fl = &bl[nj >> 1][(nj & 1)*2];
                    mma16816(acc[mi][nj], ah[mi], fh);
                    mma16816(acc[mi][nj], ah[mi], fl);
                    mma16816(acc[mi][nj], al[mi], fh);
                }
        }
        __syncthreads();
    }
    // epilogue
#pragma unroll
    for (int mi = 0; mi < 4; mi++)
#pragma unroll
    for (int nj = 0; nj < 4; nj++){
        int n = n0 + wn + nj*8 + (lane & 3)*2;
        float b0 = bias[n], b1 = bias[n+1];
#pragma unroll
        for (int h = 0; h < 2; h++){
            int m = m0 + wm + mi*16 + (lane >> 2) + h*8;
            if (m < M){
                size_t off;
                if (mode == 1){
                    int t = m >> 5, b = m & 31;
                    off = ((size_t)b*Tz + t)*(size_t)N + n;
                } else {
                    off = (size_t)m*N + n;
                }
                out[off]   = acc[mi][nj][h*2]   + b0;
                out[off+1] = acc[mi][nj][h*2+1] + b1;
            }
        }
    }
}

// ------------------------------- tail ------------------------------------
__global__ void k_tail(const int* __restrict__ sent, const int* __restrict__ slen,
                       float* __restrict__ out, long out_size){
    long base = (long)Bz*Tz*Vz;             // 130048000
    int i = blockIdx.x*blockDim.x + threadIdx.x;
    if (i < Bz*Sz && base + i < out_size)            out[base+i] = (float)sent[i];
    if (i < Bz && base + Bz*Sz + i < out_size)       out[base+Bz*Sz+i] = (float)slen[i];
}

// ------------------------------ host side --------------------------------
extern "C" void kernel_launch(void* const* d_in, const int* in_sizes, int n_in,
                              void* d_out, int out_size) {
    const float* ent   = (const float*)d_in[0];
    const float* neigh = (const float*)d_in[1];
    const int*   nnum  = (const int*)  d_in[2];
    const float* img   = (const float*)d_in[3];
    const int*   sent  = (const int*)  d_in[4];
    const int*   slen  = (const int*)  d_in[5];
    const float* emb   = (const float*)d_in[6];
    const float* W_ih  = (const float*)d_in[7];
    const float* W_hh  = (const float*)d_in[8];
    const float* b_ih  = (const float*)d_in[9];
    const float* b_hh  = (const float*)d_in[10];
    const float* W_img = (const float*)d_in[11];
    const float* b_img = (const float*)d_in[12];
    const float* W_out = (const float*)d_in[13];
    const float* b_out = (const float*)d_in[14];
    const float* Wq = (const float*)d_in[15]; const float* bq = (const float*)d_in[16];
    const float* Wk = (const float*)d_in[17]; const float* bk = (const float*)d_in[18];
    const float* Wv = (const float*)d_in[19]; const float* bv = (const float*)d_in[20];
    const float* Wo = (const float*)d_in[21]; const float* bo = (const float*)d_in[22];
    float* out = (float*)d_out;

    void *pWout_hi, *pWout_lo, *pWih_hi, *pWih_lo, *pWhh_hi, *pWhh_lo;
    void *pXhi, *pXlo, *pXg, *pHhi, *pHlo, *pBsum;
    void *pQ, *pKb, *pVb, *pCtx, *pAtt, *pFf, *pIe, *pG0;
    cudaGetSymbolAddress(&pWout_hi, g_Wout_hi); cudaGetSymbolAddress(&pWout_lo, g_Wout_lo);
    cudaGetSymbolAddress(&pWih_hi,  g_Wih_hi);  cudaGetSymbolAddress(&pWih_lo,  g_Wih_lo);
    cudaGetSymbolAddress(&pWhh_hi,  g_Whh_hi);  cudaGetSymbolAddress(&pWhh_lo,  g_Whh_lo);
    cudaGetSymbolAddress(&pXhi, g_X_hi); cudaGetSymbolAddress(&pXlo, g_X_lo);
    cudaGetSymbolAddress(&pXg,  g_Xg);   cudaGetSymbolAddress(&pBsum, g_bsum);
    cudaGetSymbolAddress(&pHhi, g_H_hi); cudaGetSymbolAddress(&pHlo, g_H_lo);
    cudaGetSymbolAddress(&pQ, g_Q); cudaGetSymbolAddress(&pKb, g_Kb);
    cudaGetSymbolAddress(&pVb, g_Vb); cudaGetSymbolAddress(&pCtx, g_ctx);
    cudaGetSymbolAddress(&pAtt, g_att); cudaGetSymbolAddress(&pFf, g_ff);
    cudaGetSymbolAddress(&pIe, g_ie); cudaGetSymbolAddress(&pG0, g_g0);

    // ---- prep: split weights to bf16 hi/lo, gather+split embeddings ----
    {
        int n = Vz*Gz;
        k_split<<<(n+255)/256, 256>>>(W_out, (bf16*)pWout_hi, (bf16*)pWout_lo, n);
        n = G4z*Ez;
        k_split<<<(n+255)/256, 256>>>(W_ih, (bf16*)pWih_hi, (bf16*)pWih_lo, n);
        n = G4z*Gz;
        k_split<<<(n+255)/256, 256>>>(W_hh, (bf16*)pWhh_hi, (bf16*)pWhh_lo, n);
        k_bsum<<<(G4z+255)/256, 256>>>(b_ih, b_hh);
        n = MR*Ez;
        k_xgather<<<(n+255)/256, 256>>>(emb, sent);
    }

    // ---- prologue: MHA + img_embed + first LSTM step ----
    k_small<<<(Bz*HIz*32+255)/256, 256>>>(ent, Wq, bq, (float*)pQ, Bz, HIz, HIz, 0);
    k_small<<<(Bz*16*HIz*32+255)/256, 256>>>(neigh, Wk, bk, (float*)pKb, Bz*16, HIz, HIz, 0);
    k_small<<<(Bz*16*HIz*32+255)/256, 256>>>(neigh, Wv, bv, (float*)pVb, Bz*16, HIz, HIz, 0);
    k_attn<<<Bz*8, 64>>>(nnum);
    k_small<<<(Bz*HIz*32+255)/256, 256>>>((const float*)pCtx, Wo, bo, (float*)pAtt, Bz, HIz, HIz, 0);
    k_ff<<<(Bz*HIz+255)/256, 256>>>(ent, img);
    k_small<<<(Bz*HIz*32+255)/256, 256>>>((const float*)pFf, W_img, b_img, (float*)pIe, Bz, HIz, 3*HIz, 1);
    k_small<<<(Bz*G4z*32+255)/256, 256>>>((const float*)pIe, W_ih, (const float*)pBsum, (float*)pG0, Bz, G4z, Ez, 0);
    k_step0<<<(Bz*Gz+255)/256, 256>>>();

    // ---- Xg = X @ W_ih^T + bsum  for all 127 steps (one GEMM) ----
    {
        dim3 grid((MR+127)/128, G4z/128);
        k_gemm3<<<grid, 256>>>((const bf16*)pXhi, (const bf16*)pXlo,
                               (const bf16*)pWih_hi, (const bf16*)pWih_lo,
                               (const float*)pBsum, (float*)pXg,
                               MR, G4z, Ez, 0);
    }

    // ---- recurrence: 127 fused steps ----
    for (int s = 0; s < Tz; s++)
        k_step<<<64, 128>>>(s);

    // ---- logits: one [4064,1024] x [1024,32000] GEMM, remapped to [B,T,V] ----
    {
        dim3 grid((MR+127)/128, Vz/128);
        k_gemm3<<<grid, 256>>>((const bf16*)pHhi + Bz*Gz, (const bf16*)pHlo + Bz*Gz,
                               (const bf16*)pWout_hi, (const bf16*)pWout_lo,
                               b_out, out, MR, Vz, Gz, 1);
    }

    // ---- tuple tail (target_sent, target_sent_len) if harness expects it ----
    if ((long)out_size > (long)Bz*Tz*Vz)
        k_tail<<<(Bz*Sz+255)/256, 256>>>(sent, slen, out, (long)out_size);
}